// round 17
// baseline (speedup 1.0000x reference)
#include <cuda_runtime.h>
#include <cstdint>

#define TASKS   128
#define NSAMP   2048
#define INDIM   256
#define OUTDIM  256
#define AP32    132                 // u32 pitch per A row; conflict-free frags
#define BP32    12                  // u32 pitch per B n-row (8 kpairs + pad); conflict-free
#define NQ      64                  // cols per CTA (quarter split)
#define KCH     16
#define NBUF    4
#define AHI_OFF 0
#define ALO_OFF (32 * AP32 * 4)
#define B_OFF   (2 * 32 * AP32 * 4)
#define BBUF_B  (2 * NQ * BP32 * 4)          // hi+lo = 6144 B per buffer
#define DYN_BYTES (B_OFF + NBUF * BBUF_B + 16)

__device__ __forceinline__ unsigned packbf(float lo, float hi) {
    unsigned r;
    asm("cvt.rn.bf16x2.f32 %0, %1, %2;" : "=r"(r) : "f"(hi), "f"(lo));
    return r;
}
__device__ __forceinline__ void split2(float x0, float x1, unsigned& h, unsigned& l) {
    h = packbf(x0, x1);
    const float h0 = __uint_as_float(h << 16);
    const float h1 = __uint_as_float(h & 0xffff0000u);
    l = packbf(x0 - h0, x1 - h1);
}
__device__ __forceinline__ void mmabf(float (&d)[4], const unsigned (&a)[4],
                                      unsigned b0, unsigned b1) {
    asm volatile(
        "mma.sync.aligned.m16n8k16.row.col.f32.bf16.bf16.f32 "
        "{%0,%1,%2,%3},{%4,%5,%6,%7},{%8,%9},{%0,%1,%2,%3};"
        : "+f"(d[0]), "+f"(d[1]), "+f"(d[2]), "+f"(d[3])
        : "r"(a[0]), "r"(a[1]), "r"(a[2]), "r"(a[3]), "r"(b0), "r"(b1));
}

// producer: load one chunk's two k-rows (even/odd of kpair p), 4 cols
__device__ __forceinline__ void prodLDG(const float* __restrict__ Wt, int kc, int p,
                                        int cg, int qb, float4& e, float4& o) {
    const float* base = Wt + (size_t)(kc * KCH + 2 * p) * OUTDIM + qb + 4 * cg;
    e = __ldg((const float4*)base);
    o = __ldg((const float4*)(base + OUTDIM));
}
__device__ __forceinline__ void prodSTS(unsigned* __restrict__ BH,
                                        unsigned* __restrict__ BL,
                                        int p, int cg, const float4& e, const float4& o) {
    const float ee[4] = { e.x, e.y, e.z, e.w };
    const float oo[4] = { o.x, o.y, o.z, o.w };
    #pragma unroll
    for (int j = 0; j < 4; ++j) {
        unsigned h, l;
        split2(ee[j], oo[j], h, l);                // (k even, k odd) -> bf16x2
        BH[(4 * cg + j) * BP32 + p] = h;
        BL[(4 * cg + j) * BP32 + p] = l;
    }
}

// consumer: one k-chunk of mma for this warp's 16 cols
__device__ __forceinline__ void consume(const unsigned* __restrict__ Ahu,
                                        const unsigned* __restrict__ Alu,
                                        const unsigned* __restrict__ BH,
                                        const unsigned* __restrict__ BL,
                                        int kc, int w, int g, int lm, bool two,
                                        float (&cacc)[2][2][4]) {
    const int ka = kc * 8 + lm;
    unsigned ah[4], al[4], ah2[4], al2[4];
    ah[0] = Ahu[(g)     * AP32 + ka];
    ah[1] = Ahu[(g + 8) * AP32 + ka];
    ah[2] = Ahu[(g)     * AP32 + ka + 4];
    ah[3] = Ahu[(g + 8) * AP32 + ka + 4];
    al[0] = Alu[(g)     * AP32 + ka];
    al[1] = Alu[(g + 8) * AP32 + ka];
    al[2] = Alu[(g)     * AP32 + ka + 4];
    al[3] = Alu[(g + 8) * AP32 + ka + 4];
    if (two) {
        ah2[0] = Ahu[(g + 16) * AP32 + ka];
        ah2[1] = Ahu[(g + 24) * AP32 + ka];
        ah2[2] = Ahu[(g + 16) * AP32 + ka + 4];
        ah2[3] = Ahu[(g + 24) * AP32 + ka + 4];
        al2[0] = Alu[(g + 16) * AP32 + ka];
        al2[1] = Alu[(g + 24) * AP32 + ka];
        al2[2] = Alu[(g + 16) * AP32 + ka + 4];
        al2[3] = Alu[(g + 24) * AP32 + ka + 4];
    }

    unsigned bh0[2], bh1[2], bl0[2], bl1[2];
    #pragma unroll
    for (int nt = 0; nt < 2; ++nt) {
        const unsigned* BHn = BH + (w * 16 + nt * 8 + g) * BP32;
        const unsigned* BLn = BL + (w * 16 + nt * 8 + g) * BP32;
        bh0[nt] = BHn[lm]; bh1[nt] = BHn[lm + 4];
        bl0[nt] = BLn[lm]; bl1[nt] = BLn[lm + 4];
    }

    mmabf(cacc[0][0], ah, bh0[0], bh1[0]);
    mmabf(cacc[0][1], ah, bh0[1], bh1[1]);
    if (two) {
        mmabf(cacc[1][0], ah2, bh0[0], bh1[0]);
        mmabf(cacc[1][1], ah2, bh0[1], bh1[1]);
    }
    mmabf(cacc[0][0], al, bh0[0], bh1[0]);
    mmabf(cacc[0][1], al, bh0[1], bh1[1]);
    if (two) {
        mmabf(cacc[1][0], al2, bh0[0], bh1[0]);
        mmabf(cacc[1][1], al2, bh0[1], bh1[1]);
    }
    mmabf(cacc[0][0], ah, bl0[0], bl1[0]);
    mmabf(cacc[0][1], ah, bl0[1], bl1[1]);
    if (two) {
        mmabf(cacc[1][0], ah2, bl0[0], bl1[0]);
        mmabf(cacc[1][1], ah2, bl0[1], bl1[1]);
    }
}

__global__ __launch_bounds__(256, 3)
void tsl_mma(const float* __restrict__ X, const void* __restrict__ TIDS,
             const float* __restrict__ W, float* __restrict__ OUT)
{
    extern __shared__ __align__(16) char dyn[];
    __shared__ unsigned short sl[NSAMP];
    __shared__ int s_cnt;
    __shared__ unsigned orv;

    const int tid = threadIdx.x, wid = tid >> 5, lane = tid & 31;
    const int g = lane >> 2, lm = lane & 3;
    const int task = blockIdx.x >> 2;
    const int quad = blockIdx.x & 3;
    const int qb = quad * NQ;

    const float* Wt = W + (size_t)task * INDIM * OUTDIM;

    if (tid == 0) { s_cnt = 0; orv = 0; }
    __syncthreads();

    // ---- ballot-compress scan ----
    const unsigned* w32 = (const unsigned*)TIDS;
    atomicOr(&orv, w32[2 * tid + 1]);              // int64 iff hi words (0..255) all 0
    __syncthreads();
    const bool is64 = (orv == 0);

    #pragma unroll 1
    for (int j = 0; j < 8; ++j) {
        const int n = j * 256 + tid;
        const int id = is64 ? (int)w32[2 * n] : (int)w32[n];
        const bool m = (id == task);
        const unsigned bal = __ballot_sync(0xffffffffu, m);
        if (bal) {
            int b = 0;
            if (lane == 0) b = atomicAdd(&s_cnt, __popc(bal));
            b = __shfl_sync(0xffffffffu, b, 0);
            if (m) sl[b + __popc(bal & ((1u << lane) - 1u))] = (unsigned short)n;
        }
    }
    __syncthreads();
    const int cnt = s_cnt;
    if (cnt == 0) return;

    unsigned* Ahu = (unsigned*)(dyn + AHI_OFF);
    unsigned* Alu = (unsigned*)(dyn + ALO_OFF);
    unsigned* Bbuf = (unsigned*)(dyn + B_OFF);     // 4 x [hi(NQ*BP32) | lo(NQ*BP32)]

    const bool isProd = (wid >= 4);
    const int pp = (tid - 128) >> 4;               // producer kpair 0..7
    const int pc = tid & 15;                       // producer col-group (4 cols)

    #pragma unroll 1
    for (int mc = 0; mc * 32 < cnt; ++mc) {
        // ---- fill A: 32 rows x 256 k as packed bf16x2 hi/lo (all 256 threads) ----
        {
            const int s = tid >> 3, q = tid & 7;
            const bool valid = (mc * 32 + s < cnt);
            const unsigned srow = valid ? (unsigned)sl[mc * 32 + s] : 0u;
            const float4* xr = (const float4*)(X + srow * INDIM) + q * 8;
            #pragma unroll
            for (int j = 0; j < 8; ++j) {
                float4 v = valid ? __ldg(xr + j) : make_float4(0.f, 0.f, 0.f, 0.f);
                unsigned h0, l0, h1, l1;
                split2(v.x, v.y, h0, l0);
                split2(v.z, v.w, h1, l1);
                const int o = s * AP32 + (q * 8 + j) * 2;
                *(uint2*)(Ahu + o) = make_uint2(h0, h1);
                *(uint2*)(Alu + o) = make_uint2(l0, l1);
            }
        }
        __syncthreads();

        const bool two = (cnt - mc * 32) > 16;
        float cacc[2][2][4];
        #pragma unroll
        for (int mt = 0; mt < 2; ++mt)
            #pragma unroll
            for (int nt = 0; nt < 2; ++nt)
                #pragma unroll
                for (int p = 0; p < 4; ++p) cacc[mt][nt][p] = 0.f;

        float4 eA, oA, eB, oB;
        if (isProd) {
            prodLDG(Wt, 0, pp, pc, qb, eA, oA);
            prodLDG(Wt, 1, pp, pc, qb, eB, oB);
        }

        #pragma unroll 1
        for (int kc = 0; kc < INDIM / KCH; kc += 2) {
            if (isProd) {
                unsigned* bb = Bbuf + (kc & 3) * (BBUF_B / 4);
                prodSTS(bb, bb + NQ * BP32, pp, pc, eA, oA);
                if (kc + 2 < INDIM / KCH) prodLDG(Wt, kc + 2, pp, pc, qb, eA, oA);
            }
            __syncthreads();
            if (!isProd) {
                const unsigned* bb = Bbuf + (kc & 3) * (BBUF_B / 4);
                consume(Ahu, Alu, bb, bb + NQ * BP32, kc, wid, g, lm, two, cacc);
            }
            if (isProd) {
                unsigned* bb = Bbuf + ((kc + 1) & 3) * (BBUF_B / 4);
                prodSTS(bb, bb + NQ * BP32, pp, pc, eB, oB);
                if (kc + 3 < INDIM / KCH) prodLDG(Wt, kc + 3, pp, pc, qb, eB, oB);
            }
            __syncthreads();
            if (!isProd) {
                const unsigned* bb = Bbuf + ((kc + 1) & 3) * (BBUF_B / 4);
                consume(Ahu, Alu, bb, bb + NQ * BP32, kc + 1, wid, g, lm, two, cacc);
            }
        }

        // ---- store (consumer warps) ----
        if (!isProd) {
            #pragma unroll
            for (int mt = 0; mt < 2; ++mt) {
                #pragma unroll
                for (int nt = 0; nt < 2; ++nt) {
                    const int col = qb + wid * 16 + nt * 8 + 2 * lm;
                    const int r0 = mc * 32 + mt * 16 + g;
                    if (r0 < cnt)
                        *(float2*)(OUT + (size_t)sl[r0] * OUTDIM + col)
                            = make_float2(cacc[mt][nt][0], cacc[mt][nt][1]);
                    const int r1 = r0 + 8;
                    if (r1 < cnt)
                        *(float2*)(OUT + (size_t)sl[r1] * OUTDIM + col)
                            = make_float2(cacc[mt][nt][2], cacc[mt][nt][3]);
                }
            }
        }
        __syncthreads();                           // guard A/B smem reuse next chunk
    }
}

extern "C" void kernel_launch(void* const* d_in, const int* in_sizes, int n_in,
                              void* d_out, int out_size)
{
    const float* X    = (const float*)d_in[0];
    const void*  TIDS = d_in[1];
    const float* W    = (const float*)d_in[2];
    float*       OUT  = (float*)d_out;

    cudaFuncSetAttribute(tsl_mma, cudaFuncAttributeMaxDynamicSharedMemorySize, DYN_BYTES);
    tsl_mma<<<4 * TASKS, 256, DYN_BYTES>>>(X, TIDS, W, OUT);
}